// round 16
// baseline (speedup 1.0000x reference)
#include <cuda_runtime.h>
#include <cuda_fp16.h>
#include <math.h>

#define N_NODES 50000
#define N_EDGES 800000
#define D 64
#define C 8

#define SCAN_BLOCK 1024
#define SCAN_NBLK ((N_NODES + SCAN_BLOCK - 1) / SCAN_BLOCK)   // 49

#define GEMM_BN 128
#define GEMM_ASTG (GEMM_BN * 144)
#define GEMM_BOFF (2 * GEMM_ASTG)
#define GEMM_BSTG (64 * 144)
#define GEMM_SMEM (GEMM_BOFF + 2 * GEMM_BSTG)  // 55296 B

typedef unsigned long long ull;

// ---------------- scratch (device globals; no allocations allowed) ----------
__device__ __half g_Z[(size_t)N_NODES * 25 * D];
__device__ __half g_hf[(size_t)N_NODES * D];
__device__ __half g_Wt1[10 * 64 * 64];
__device__ __half g_Wt2[26 * 64 * 64];
__device__ __half g_Wm1[64 * 64];
__device__ __half g_Wm2[64 * 8];
__device__ int    g_cnt[N_NODES];
__device__ int    g_off[N_NODES + 1];
__device__ int    g_fill[N_NODES];
__device__ int    g_part[SCAN_NBLK];
__device__ int    g_order[N_EDGES];

// ---------------- helpers ----------------------------------------------------
__device__ __forceinline__ unsigned packh2(float a, float b) {
    __half2 h = __floats2half2_rn(a, b);
    return *reinterpret_cast<unsigned*>(&h);
}

#define LDSM4(r0, r1, r2, r3, addr)                                          \
    asm volatile("ldmatrix.sync.aligned.m8n8.x4.shared.b16 {%0,%1,%2,%3}, [%4];" \
                 : "=r"(r0), "=r"(r1), "=r"(r2), "=r"(r3) : "r"(addr))

#define LDSM4T(r0, r1, r2, r3, addr)                                         \
    asm volatile("ldmatrix.sync.aligned.m8n8.x4.trans.shared.b16 {%0,%1,%2,%3}, [%4];" \
                 : "=r"(r0), "=r"(r1), "=r"(r2), "=r"(r3) : "r"(addr))

#define MMA16816(d, a0, a1, a2, a3, b0, b1)                                  \
    asm volatile("mma.sync.aligned.m16n8k16.row.col.f32.f16.f16.f32 "        \
                 "{%0,%1,%2,%3}, {%4,%5,%6,%7}, {%8,%9}, {%0,%1,%2,%3};"     \
                 : "+f"(d[0]), "+f"(d[1]), "+f"(d[2]), "+f"(d[3])            \
                 : "r"(a0), "r"(a1), "r"(a2), "r"(a3), "r"(b0), "r"(b1))

// ---------------- weight conversion ------------------------------------------
__global__ void convw_kernel(const float* __restrict__ W1, const float* __restrict__ root1,
                             const float* __restrict__ W2, const float* __restrict__ root2,
                             const float* __restrict__ m1w, const float* __restrict__ m2w) {
    int i = blockIdx.x * blockDim.x + threadIdx.x;
    if (i < 37 * 1024) {
        int slot = i >> 10;
        int rem = i & 1023;
        int o = rem >> 4;
        int d4 = (rem & 15) * 4;
        const float* src;
        __half* dst;
        if (slot < 10) {
            src = (slot < 9) ? W1 + slot * 4096 : root1;
            dst = g_Wt1 + slot * 4096;
        } else if (slot < 36) {
            int s = slot - 10;
            src = (s < 25) ? W2 + s * 4096 : root2;
            dst = g_Wt2 + s * 4096;
        } else {
            src = m1w;
            dst = g_Wm1;
        }
        __half h[4];
#pragma unroll
        for (int j = 0; j < 4; j++) h[j] = __float2half(src[(d4 + j) * 64 + o]);
        *reinterpret_cast<ull*>(dst + o * 64 + d4) = *reinterpret_cast<ull*>(h);
    } else if (i < 37 * 1024 + 128) {
        int j = i - 37 * 1024;
        __half h[4];
#pragma unroll
        for (int t = 0; t < 4; t++) h[t] = __float2half(m2w[4 * j + t]);
        *reinterpret_cast<ull*>(g_Wm2 + 4 * j) = *reinterpret_cast<ull*>(h);
    }
}

// ---------------- CSR build ---------------------------------------------------
__global__ void hist_kernel(const int* __restrict__ ei, const float* __restrict__ x) {
    int e = blockIdx.x * blockDim.x + threadIdx.x;
    if (e < N_EDGES) atomicAdd(&g_cnt[ei[N_EDGES + e]], 1);
    if (e < N_NODES) g_fill[e] = 0;
    if (e < N_NODES * D / 4) {
        float4 v = reinterpret_cast<const float4*>(x)[e];
        reinterpret_cast<__half2*>(g_hf)[2 * e]     = __floats2half2_rn(v.x, v.y);
        reinterpret_cast<__half2*>(g_hf)[2 * e + 1] = __floats2half2_rn(v.z, v.w);
    }
}

__global__ void scan1_kernel() {
    __shared__ int wsum[32];
    int tid = threadIdx.x;
    int lane = tid & 31, w = tid >> 5;
    int i = blockIdx.x * SCAN_BLOCK + tid;
    int v = (i < N_NODES) ? g_cnt[i] : 0;
    int s = v;
#pragma unroll
    for (int o = 1; o < 32; o <<= 1) {
        int t = __shfl_up_sync(0xffffffffu, s, o);
        if (lane >= o) s += t;
    }
    if (lane == 31) wsum[w] = s;
    __syncthreads();
    if (w == 0) {
        int t = wsum[lane];
#pragma unroll
        for (int o = 1; o < 32; o <<= 1) {
            int u = __shfl_up_sync(0xffffffffu, t, o);
            if (lane >= o) t += u;
        }
        wsum[lane] = t;
    }
    __syncthreads();
    int base = (w > 0) ? wsum[w - 1] : 0;
    int incl = base + s;
    if (i < N_NODES) g_off[i] = incl - v;
    if (tid == SCAN_BLOCK - 1) g_part[blockIdx.x] = incl;
}

__global__ void scan2_kernel() {
    if (threadIdx.x == 0) {
        int run = 0;
#pragma unroll
        for (int b = 0; b < SCAN_NBLK; b++) {
            int t = g_part[b];
            g_part[b] = run;
            run += t;
        }
    }
}

__global__ void scan3_kernel() {
    int i = blockIdx.x * SCAN_BLOCK + threadIdx.x;
    if (i < N_NODES) g_off[i] += g_part[blockIdx.x];
    if (i == 0) g_off[N_NODES] = N_EDGES;
}

__global__ void scatter_kernel(const int* __restrict__ ei) {
    int e = blockIdx.x * blockDim.x + threadIdx.x;
    if (e < N_EDGES) {
        int dst = ei[N_EDGES + e];
        int pos = g_off[dst] + atomicAdd(&g_fill[dst], 1);
        g_order[pos] = e;
    }
    if (e < N_NODES) g_cnt[e] = 0;
}

// ---------------- edge aggregation on TENSOR CORES ----------------------------
// Per warp = one dst node. Per 32-edge chunk:
//   Bmat[k][e] (KEpad x 32, fp16, zeroed + scattered basis weights)
//   Xs[e][d]   (32 x 64 fp16, gathered rows; all rows valid via clamped src)
//   Z (D frags) += Bmat @ Xs  -- A: non-trans ldmatrix (validated gemm pattern),
//                               B: ldmatrix.x4.trans (pairs (r0,r1),(r2,r3)).
// ks=1 (e-cols 16..31) skipped when cnt<=16 (those Bmat cols are zero).
#define BST 40   // Bmat row stride (halfs): rows 0..7 hit distinct bank groups
#define XST 72   // Xs row stride (halfs): 144B, validated conflict-free

template<int K>
__global__ void __launch_bounds__(64)
aggregate_kernel(const __half* __restrict__ hin,
                 const int* __restrict__ ei,
                 const float* __restrict__ ea) {
    const int KE = K * K;
    const int MT = (KE + 15) / 16;          // m-tiles (1 for K=3, 2 for K=5)
    __shared__ __half Bm[2][MT * 16 * BST];
    __shared__ __half Xs[2][32 * XST];
    __shared__ int    m_src[2][32];

    const int g = threadIdx.x >> 5;
    const int lane = threadIdx.x & 31;
    const int n = blockIdx.x * 2 + g;
    const bool active = n < N_NODES;

    float dacc[MT][8][4];
#pragma unroll
    for (int mt = 0; mt < MT; mt++)
#pragma unroll
        for (int nt = 0; nt < 8; nt++)
#pragma unroll
            for (int i = 0; i < 4; i++) dacc[mt][nt][i] = 0.0f;

    int e0 = 0, e1 = 0;
    if (active) { e0 = g_off[n]; e1 = g_off[n + 1]; }

    const unsigned bm0 = (unsigned)__cvta_generic_to_shared(&Bm[g][0]);
    const unsigned xs0 = (unsigned)__cvta_generic_to_shared(&Xs[g][0]);
    // A fragment lane address (identical scheme to validated gemm kernel)
    const unsigned a_addr = bm0
        + ((lane & 7) + ((lane >> 3) & 1) * 8) * (BST * 2) + (lane >> 4) * 16;
    // B fragment lane address for trans: rows = lane&15, +16B for lanes 16-31
    const unsigned b_addr = xs0 + (lane & 15) * (XST * 2) + (lane >> 4) * 16;

    for (int c = e0; c < e1; c += 32) {
        int cnt = min(32, e1 - c);

        // zero Bmat (full region incl. padding)
#pragma unroll
        for (int i = lane; i < MT * 16 * BST / 8; i += 32)
            reinterpret_cast<float4*>(&Bm[g][0])[i] = make_float4(0.f, 0.f, 0.f, 0.f);
        __syncwarp();

        // metadata + basis scatter (clamped index keeps all 32 src rows valid)
        {
            int e = g_order[c + min(lane, cnt - 1)];
            int src = ei[e];
            m_src[g][lane] = src;
            if (lane < cnt) {
                float p0 = ea[2 * e + 0];
                float p1 = ea[2 * e + 1];
                float v0 = p0 * (float)(K - 1);
                int l0 = min((int)v0, K - 2);
                float f0 = v0 - (float)l0;
                float v1 = p1 * (float)(K - 1);
                int l1 = min((int)v1, K - 2);
                float f1 = v1 - (float)l1;
                float b00 = 1.0f - f0, b01 = f0;
                float b10 = 1.0f - f1, b11 = f1;
                int kbase = l0 + l1 * K;
                Bm[g][kbase * BST + lane]           = __float2half(b00 * b10);
                Bm[g][(kbase + K) * BST + lane]     = __float2half(b00 * b11);
                Bm[g][(kbase + 1) * BST + lane]     = __float2half(b01 * b10);
                Bm[g][(kbase + K + 1) * BST + lane] = __float2half(b01 * b11);
            }
        }
        __syncwarp();

        // gather X rows (8 passes; each 8-lane group loads one 128B row)
#pragma unroll
        for (int p = 0; p < 8; p++) {
            int r = p * 4 + (lane >> 3);
            int s = m_src[g][r];
            int q = lane & 7;
            *reinterpret_cast<float4*>(&Xs[g][r * XST + q * 8]) =
                *reinterpret_cast<const float4*>(hin + (size_t)s * D + q * 8);
        }
        __syncwarp();

        // MMA: Z(KEpad x 64) += Bmat(KEpad x 32) @ Xs(32 x 64)
        int ksmax = (cnt > 16) ? 2 : 1;
        for (int ks = 0; ks < ksmax; ks++) {
            unsigned a[MT][4];
#pragma unroll
            for (int mt = 0; mt < MT; mt++)
                LDSM4(a[mt][0], a[mt][1], a[mt][2], a[mt][3],
                      a_addr + mt * 16 * (BST * 2) + ks * 32);
#pragma unroll
            for (int nt2 = 0; nt2 < 4; nt2++) {
                unsigned r0, r1, r2, r3;
                LDSM4T(r0, r1, r2, r3, b_addr + ks * 16 * (XST * 2) + nt2 * 32);
#pragma unroll
                for (int mt = 0; mt < MT; mt++) {
                    MMA16816(dacc[mt][2 * nt2],     a[mt][0], a[mt][1], a[mt][2], a[mt][3], r0, r1);
                    MMA16816(dacc[mt][2 * nt2 + 1], a[mt][0], a[mt][1], a[mt][2], a[mt][3], r2, r3);
                }
            }
        }
        __syncwarp();
    }

    if (active) {
        float invc = 1.0f / fmaxf((float)(e1 - e0), 1.0f);
        __half* zout = g_Z + (size_t)n * KE * D;
        const int gr = lane >> 2;
        const int tig = lane & 3;
#pragma unroll
        for (int mt = 0; mt < MT; mt++) {
            int kA = mt * 16 + gr;
            int kB = kA + 8;
#pragma unroll
            for (int nt = 0; nt < 8; nt++) {
                int col = nt * 8 + 2 * tig;
                if (kA < KE)
                    *reinterpret_cast<__half2*>(zout + kA * D + col) =
                        __floats2half2_rn(dacc[mt][nt][0] * invc, dacc[mt][nt][1] * invc);
                if (kB < KE)
                    *reinterpret_cast<__half2*>(zout + kB * D + col) =
                        __floats2half2_rn(dacc[mt][nt][2] * invc, dacc[mt][nt][3] * invc);
            }
        }
    }
}

// ---------------- tensor-core GEMM: 128-node M-tile (R15 exact) ---------------
template<int KE>
__global__ void __launch_bounds__(256)
gemm_kernel(const __half* __restrict__ Z,
            const __half* __restrict__ hf,
            const __half* __restrict__ Wt,
            const float* __restrict__ bias,
            __half* __restrict__ houtH) {
    const int KS = KE + 1;
    extern __shared__ __align__(16) char smraw[];

    const int tid = threadIdx.x;
    const int warp = tid >> 5, lane = tid & 31;
    const int n0 = blockIdx.x * GEMM_BN;
    const int m_base = warp * 16;

    float d[32];
#pragma unroll
    for (int i = 0; i < 32; i++) d[i] = 0.0f;

    const unsigned s0 = (unsigned)__cvta_generic_to_shared(smraw);
    const unsigned a_lane = s0
        + (m_base + (lane & 7) + ((lane >> 3) & 1) * 8) * 144 + (lane >> 4) * 16;
    const unsigned b_lane = s0 + GEMM_BOFF
        + ((lane & 7) + ((lane >> 3) & 1) * 8) * 144 + (lane >> 4) * 16;

    auto prefetch = [&](int k, int stage) {
#pragma unroll
        for (int i = 0; i < 4; i++) {
            int c = tid + i * 256;
            int row = c >> 3, q = c & 7;
            int n = n0 + row;
            if (n > N_NODES - 1) n = N_NODES - 1;
            const __half* src = (k < KE)
                ? (Z + ((size_t)n * KE + k) * D + q * 8)
                : (hf + (size_t)n * D + q * 8);
            unsigned sa = s0 + stage * GEMM_ASTG + row * 144 + q * 16;
            asm volatile("cp.async.ca.shared.global [%0], [%1], 16;" :: "r"(sa), "l"(src));
        }
        const __half* wsrc = Wt + (size_t)k * 4096;
#pragma unroll
        for (int i = 0; i < 2; i++) {
            int c = tid + i * 256;
            int row = c >> 3, q = c & 7;
            unsigned sa = s0 + GEMM_BOFF + stage * GEMM_BSTG + row * 144 + q * 16;
            asm volatile("cp.async.ca.shared.global [%0], [%1], 16;" :: "r"(sa), "l"(wsrc + row * 64 + q * 8));
        }
        asm volatile("cp.async.commit_group;");
    };

    prefetch(0, 0);
    int buf = 0;
    for (int k = 0; k < KS; k++) {
        if (k + 1 < KS) {
            prefetch(k + 1, buf ^ 1);
            asm volatile("cp.async.wait_group 1;");
        } else {
            asm volatile("cp.async.wait_group 0;");
        }
        __syncthreads();

        unsigned ab = a_lane + buf * GEMM_ASTG;
        unsigned bb = b_lane + buf * GEMM_BSTG;
#pragma unroll
        for (int kc = 0; kc < 4; kc++) {
            unsigned a0, a1, a2, a3;
            LDSM4(a0, a1, a2, a3, ab + kc * 32);
#pragma unroll
            for (int nt2 = 0; nt2 < 4; nt2++) {
                unsigned r0, r1, r2, r3;
                LDSM4(r0, r1, r2, r3, bb + nt2 * 2304 + kc * 32);
                MMA16816((d + (2 * nt2) * 4),     a0, a1, a2, a3, r0, r2);
                MMA16816((d + (2 * nt2 + 1) * 4), a0, a1, a2, a3, r1, r3);
            }
        }
        __syncthreads();
        buf ^= 1;
    }

    const int g = lane >> 2;
    const int tig = lane & 3;
    const int nA = n0 + m_base + g;
    const int nB = nA + 8;
#pragma unroll
    for (int nt = 0; nt < 8; nt++) {
        int ncol = nt * 8 + 2 * tig;
        float bb0 = bias[ncol], bb1 = bias[ncol + 1];
        float v00 = d[nt * 4 + 0] + bb0;
        float v01 = d[nt * 4 + 1] + bb1;
        float v10 = d[nt * 4 + 2] + bb0;
        float v11 = d[nt * 4 + 3] + bb1;
        v00 = (v00 > 0.0f) ? v00 : expm1f(v00);
        v01 = (v01 > 0.0f) ? v01 : expm1f(v01);
        v10 = (v10 > 0.0f) ? v10 : expm1f(v10);
        v11 = (v11 > 0.0f) ? v11 : expm1f(v11);
        if (nA < N_NODES)
            *reinterpret_cast<__half2*>(houtH + (size_t)nA * D + ncol) =
                __floats2half2_rn(v00, v01);
        if (nB < N_NODES)
            *reinterpret_cast<__half2*>(houtH + (size_t)nB * D + ncol) =
                __floats2half2_rn(v10, v11);
    }
}

// ---------------- MLP tail on tensor cores (R14 exact) ------------------------
__global__ void __launch_bounds__(128)
mlp_mma_kernel(const __half* __restrict__ hf,
               const __half* __restrict__ Wm1,
               const __half* __restrict__ Wm2,
               const float* __restrict__ b1,
               const float* __restrict__ b2,
               float* __restrict__ out) {
    __shared__ __align__(16) __half As[64][72];
    __shared__ __align__(16) __half Bs[64][72];
    __shared__ __align__(8)  __half w2s[512];

    const int tid = threadIdx.x;
    const int warp = tid >> 5, lane = tid & 31;
    const int n0 = blockIdx.x * 64;
    const int m_base = warp * 16;

    const unsigned a0s = (unsigned)__cvta_generic_to_shared(&As[0][0]);
    const unsigned b0s = (unsigned)__cvta_generic_to_shared(&Bs[0][0]);

#pragma unroll
    for (int i = 0; i < 4; i++) {
        int c = tid + i * 128;
        int row = c >> 3, q = c & 7;
        int n = n0 + row;
        if (n > N_NODES - 1) n = N_NODES - 1;
        unsigned sa = a0s + row * 144 + q * 16;
        asm volatile("cp.async.ca.shared.global [%0], [%1], 16;" :: "r"(sa), "l"(hf + (size_t)n * D + q * 8));
        unsigned sb = b0s + row * 144 + q * 16;
        asm volatile("cp.async.ca.shared.global [%0], [%1], 16;" :: "r"(sb), "l"(Wm1 + row * 64 + q * 8));
    }
    *reinterpret_cast<ull*>(w2s + tid * 4) = *reinterpret_cast<const ull*>(Wm2 + tid * 4);
    asm volatile("cp.async.commit_group;");
    asm volatile("cp.async.wait_group 0;");
    __syncthreads();

    const unsigned a_lane = a0s
        + (m_base + (lane & 7) + ((lane >> 3) & 1) * 8) * 144 + (lane >> 4) * 16;
    const unsigned b_lane = b0s
        + ((lane & 7) + ((lane >> 3) & 1) * 8) * 144 + (lane >> 4) * 16;

    float d[32];
#pragma unroll
    for (int i = 0; i < 32; i++) d[i] = 0.0f;

#pragma unroll
    for (int kc = 0; kc < 4; kc++) {
        unsigned a0, a1, a2, a3;
        LDSM4(a0, a1, a2, a3, a_lane + kc * 32);
#pragma unroll
        for (int nt2 = 0; nt2 < 4; nt2++) {
            unsigned r0, r1, r2, r3;
            LDSM4(r0, r1, r2, r3, b_lane + nt2 * 2304 + kc * 32);
            MMA16816((d + (2 * nt2) * 4),     a0, a1, a2, a3, r0, r2);
            MMA16816((d + (2 * nt2 + 1) * 4), a0, a1, a2, a3, r1, r3);
        }
    }

    const int g = lane >> 2;
    const int tig = lane & 3;
    float t[32];
#pragma unroll
    for (int nt = 0; nt < 8; nt++) {
        int ncol = nt * 8 + 2 * tig;
        float bb0 = b1[ncol], bb1 = b1[ncol + 1];
        t[nt * 4 + 0] = fmaxf(d[nt * 4 + 0] + bb0, 0.0f);
        t[nt * 4 + 1] = fmaxf(d[nt * 4 + 1] + bb1, 0.0f);
        t[nt * 4 + 2] = fmaxf(d[nt * 4 + 2] + bb0, 0.0f);
        t[nt * 4 + 3] = fmaxf(d[nt * 4 + 3] + bb1, 0.0f);
    }

    float o4[4] = {0.0f, 0.0f, 0.0f, 0.0f};
#pragma unroll
    for (int kc = 0; kc < 4; kc++) {
        int nt0 = 2 * kc, nt1 = 2 * kc + 1;
        unsigned a0 = packh2(t[nt0 * 4 + 0], t[nt0 * 4 + 1]);
        unsigned a1 = packh2(t[nt0 * 4 + 2], t[nt0 * 4 + 3]);
        unsigned a2 = packh2(t[nt1 * 4 + 0], t[nt1 * 4 + 1]);
        unsigned a3 = packh2(t[nt1 * 4 + 2], t[nt1 * 4 + 3]);
        int k0 = 16 * kc + 2 * tig;
        unsigned bf0 = packh2(__half2float(w2s[k0 * 8 + g]),
                              __half2float(w2s[(k0 + 1) * 8 + g]));
        unsigned bf1 = packh2(__half2float(w2s[(k0 + 8) * 8 + g]),
                              __half2float(w2s[(k0 + 9) * 8 + g]));
        MMA16816(o4, a0, a1, a2, a3, bf0, bf1);
    }

    const int nA = n0 + m_base + g;
    const int nB = nA + 8;
    float bb0 = b2[2 * tig], bb1 = b2[2 * tig + 1];
    if (nA < N_NODES)
        *reinterpret_cast<float2*>(out + (size_t)nA * C + 2 * tig) =
            make_float2(fmaxf(o4[0] + bb0, 0.0f), fmaxf(o4[1] + bb1, 0.0f));
    if (nB < N_NODES)
        *reinterpret_cast<float2*>(out + (size_t)nB * C + 2 * tig) =
            make_float2(fmaxf(o4[2] + bb0, 0.0f), fmaxf(o4[3] + bb1, 0.0f));
}

// ---------------- launch -----------------------------------------------------
extern "C" void kernel_launch(void* const* d_in, const int* in_sizes, int n_in,
                              void* d_out, int out_size) {
    const float* x     = (const float*)d_in[0];
    const int*   ei    = (const int*)  d_in[1];
    const float* ea    = (const float*)d_in[2];
    const float* W1    = (const float*)d_in[3];
    const float* root1 = (const float*)d_in[4];
    const float* b1    = (const float*)d_in[5];
    const float* W2    = (const float*)d_in[6];
    const float* root2 = (const float*)d_in[7];
    const float* b2    = (const float*)d_in[8];
    const float* m1w   = (const float*)d_in[9];
    const float* m1b   = (const float*)d_in[10];
    const float* m2w   = (const float*)d_in[11];
    const float* m2b   = (const float*)d_in[12];
    float* out = (float*)d_out;

    __half* gZ;   cudaGetSymbolAddress((void**)&gZ, g_Z);
    __half* ghf;  cudaGetSymbolAddress((void**)&ghf, g_hf);
    __half* gWt1; cudaGetSymbolAddress((void**)&gWt1, g_Wt1);
    __half* gWt2; cudaGetSymbolAddress((void**)&gWt2, g_Wt2);
    __half* gWm1; cudaGetSymbolAddress((void**)&gWm1, g_Wm1);
    __half* gWm2; cudaGetSymbolAddress((void**)&gWm2, g_Wm2);

    cudaFuncSetAttribute((const void*)gemm_kernel<9>,
                         cudaFuncAttributeMaxDynamicSharedMemorySize, GEMM_SMEM);
    cudaFuncSetAttribute((const void*)gemm_kernel<25>,
                         cudaFuncAttributeMaxDynamicSharedMemorySize, GEMM_SMEM);

    const int GEMM_BLOCKS = (N_NODES + GEMM_BN - 1) / GEMM_BN;   // 391
    const int AGG_BLOCKS  = (N_NODES + 1) / 2;                   // 25000
    const int MLP_BLOCKS  = (N_NODES + 63) / 64;                 // 782
    const int EB = (N_EDGES + 255) / 256;                        // 3125

    // ---- CSR build ----
    hist_kernel<<<EB, 256>>>(ei, x);
    scan1_kernel<<<SCAN_NBLK, SCAN_BLOCK>>>();
    scan2_kernel<<<1, 32>>>();
    scan3_kernel<<<SCAN_NBLK, SCAN_BLOCK>>>();
    scatter_kernel<<<EB, 256>>>(ei);
    convw_kernel<<<(37 * 1024 + 128 + 255) / 256, 256>>>(W1, root1, W2, root2, m1w, m2w);

    // ---- Layer 1 (K=3) ----
    aggregate_kernel<3><<<AGG_BLOCKS, 64>>>(ghf, ei, ea);
    gemm_kernel<9><<<GEMM_BLOCKS, 256, GEMM_SMEM>>>(gZ, ghf, gWt1, b1, ghf);

    // ---- Layer 2 (K=5) ----
    aggregate_kernel<5><<<AGG_BLOCKS, 64>>>(ghf, ei, ea);
    gemm_kernel<25><<<GEMM_BLOCKS, 256, GEMM_SMEM>>>(gZ, ghf, gWt2, b2, ghf);

    // ---- MLP tail on tensor cores ----
    mlp_mma_kernel<<<MLP_BLOCKS, 128>>>(ghf, gWm1, gWm2, m1b, m2b, out);
}

// round 17
// speedup vs baseline: 1.0327x; 1.0327x over previous
#include <cuda_runtime.h>
#include <cuda_fp16.h>
#include <math.h>

#define N_NODES 50000
#define N_EDGES 800000
#define D 64
#define C 8

#define SCAN_BLOCK 1024
#define SCAN_NBLK ((N_NODES + SCAN_BLOCK - 1) / SCAN_BLOCK)   // 49

#define GEMM_BN 128
#define GEMM_ASTG (GEMM_BN * 144)
#define GEMM_BOFF (2 * GEMM_ASTG)
#define GEMM_BSTG (64 * 144)
#define GEMM_SMEM (GEMM_BOFF + 2 * GEMM_BSTG)  // 55296 B

typedef unsigned long long ull;

// ---------------- scratch (device globals; no allocations allowed) ----------
__device__ __half g_Z[(size_t)N_NODES * 25 * D];
__device__ __half g_hf[(size_t)N_NODES * D];
__device__ __half g_Wt1[10 * 64 * 64];
__device__ __half g_Wt2[26 * 64 * 64];
__device__ __half g_Wm1[64 * 64];
__device__ __half g_Wm2[64 * 8];
__device__ int    g_cnt[N_NODES];
__device__ int    g_off[N_NODES + 1];
__device__ int    g_fill[N_NODES];
__device__ int    g_part[SCAN_NBLK];
__device__ int    g_order[N_EDGES];

// ---------------- helpers ----------------------------------------------------
__device__ __forceinline__ ull pack2(float x) {
    ull r;
    asm("mov.b64 %0, {%1, %1};" : "=l"(r) : "f"(x));
    return r;
}
__device__ __forceinline__ ull packf2(float a, float b) {
    ull r;
    asm("mov.b64 %0, {%1, %2};" : "=l"(r) : "f"(a), "f"(b));
    return r;
}
__device__ __forceinline__ void fma2(ull &acc, ull a, ull b) {
    asm("fma.rn.f32x2 %0, %1, %2, %3;" : "=l"(acc) : "l"(a), "l"(b), "l"(acc));
}
__device__ __forceinline__ float2 unpack2(ull v) {
    float2 f;
    asm("mov.b64 {%0, %1}, %2;" : "=f"(f.x), "=f"(f.y) : "l"(v));
    return f;
}
__device__ __forceinline__ unsigned packh2(float a, float b) {
    __half2 h = __floats2half2_rn(a, b);
    return *reinterpret_cast<unsigned*>(&h);
}

#define LDSM4(r0, r1, r2, r3, addr)                                          \
    asm volatile("ldmatrix.sync.aligned.m8n8.x4.shared.b16 {%0,%1,%2,%3}, [%4];" \
                 : "=r"(r0), "=r"(r1), "=r"(r2), "=r"(r3) : "r"(addr))

#define MMA16816(d, a0, a1, a2, a3, b0, b1)                                  \
    asm volatile("mma.sync.aligned.m16n8k16.row.col.f32.f16.f16.f32 "        \
                 "{%0,%1,%2,%3}, {%4,%5,%6,%7}, {%8,%9}, {%0,%1,%2,%3};"     \
                 : "+f"(d[0]), "+f"(d[1]), "+f"(d[2]), "+f"(d[3])            \
                 : "r"(a0), "r"(a1), "r"(a2), "r"(a3), "r"(b0), "r"(b1))

// ---------------- CSR build (x->fp16 conversion folded into hist) ------------
__global__ void hist_kernel(const int* __restrict__ ei, const float* __restrict__ x) {
    int e = blockIdx.x * blockDim.x + threadIdx.x;
    if (e < N_EDGES) atomicAdd(&g_cnt[ei[N_EDGES + e]], 1);
    if (e < N_NODES) g_fill[e] = 0;
    if (e < N_NODES * D / 4) {
        float4 v = reinterpret_cast<const float4*>(x)[e];
        reinterpret_cast<__half2*>(g_hf)[2 * e]     = __floats2half2_rn(v.x, v.y);
        reinterpret_cast<__half2*>(g_hf)[2 * e + 1] = __floats2half2_rn(v.z, v.w);
    }
}

// scan1 (warp-shuffle block scan) + weight conversion folded in (free lanes)
__global__ void scan1_kernel(const float* __restrict__ W1, const float* __restrict__ root1,
                             const float* __restrict__ W2, const float* __restrict__ root2,
                             const float* __restrict__ m1w, const float* __restrict__ m2w) {
    __shared__ int wsum[32];
    int tid = threadIdx.x;
    int lane = tid & 31, w = tid >> 5;
    int i = blockIdx.x * SCAN_BLOCK + tid;
    int v = (i < N_NODES) ? g_cnt[i] : 0;
    int s = v;
#pragma unroll
    for (int o = 1; o < 32; o <<= 1) {
        int t = __shfl_up_sync(0xffffffffu, s, o);
        if (lane >= o) s += t;
    }
    if (lane == 31) wsum[w] = s;

    // ---- folded weight conversion (independent of the scan) ----
    {
        int j = i;   // global thread id over 49*1024 = 50176 >= 38016 items
        if (j < 37 * 1024) {
            int slot = j >> 10;
            int rem = j & 1023;
            int o = rem >> 4;
            int d4 = (rem & 15) * 4;
            const float* src;
            __half* dst;
            if (slot < 10) {
                src = (slot < 9) ? W1 + slot * 4096 : root1;
                dst = g_Wt1 + slot * 4096;
            } else if (slot < 36) {
                int sidx = slot - 10;
                src = (sidx < 25) ? W2 + sidx * 4096 : root2;
                dst = g_Wt2 + sidx * 4096;
            } else {
                src = m1w;
                dst = g_Wm1;
            }
            __half h[4];
#pragma unroll
            for (int t = 0; t < 4; t++) h[t] = __float2half(src[(d4 + t) * 64 + o]);
            *reinterpret_cast<ull*>(dst + o * 64 + d4) = *reinterpret_cast<ull*>(h);
        } else if (j < 37 * 1024 + 128) {
            int jj = j - 37 * 1024;
            __half h[4];
#pragma unroll
            for (int t = 0; t < 4; t++) h[t] = __float2half(m2w[4 * jj + t]);
            *reinterpret_cast<ull*>(g_Wm2 + 4 * jj) = *reinterpret_cast<ull*>(h);
        }
    }

    __syncthreads();
    if (w == 0) {
        int t = wsum[lane];
#pragma unroll
        for (int o = 1; o < 32; o <<= 1) {
            int u = __shfl_up_sync(0xffffffffu, t, o);
            if (lane >= o) t += u;
        }
        wsum[lane] = t;
    }
    __syncthreads();
    int base = (w > 0) ? wsum[w - 1] : 0;
    int incl = base + s;
    if (i < N_NODES) g_off[i] = incl - v;
    if (tid == SCAN_BLOCK - 1) g_part[blockIdx.x] = incl;
}

// merged scan2+scan3: each block re-derives the partial prefix via one
// warp-shuffle scan over the 49 g_part values (cheap, redundant, removes the
// single-block scan2 kernel and its serialization).
__global__ void scan23_kernel() {
    __shared__ int base_sh;
    int tid = threadIdx.x;
    if (tid < 32) {
        int p = (tid < SCAN_NBLK) ? g_part[tid] : 0;   // SCAN_NBLK=49 > 32!
        // need 49 values: handle with two loads
        int p2 = (tid + 32 < SCAN_NBLK) ? g_part[tid + 32] : 0;
        // inclusive scan of first 32
        int s = p;
#pragma unroll
        for (int o = 1; o < 32; o <<= 1) {
            int t = __shfl_up_sync(0xffffffffu, s, o);
            if (tid >= o) s += t;
        }
        int total32 = __shfl_sync(0xffffffffu, s, 31);
        // inclusive scan of second 17
        int s2 = p2;
#pragma unroll
        for (int o = 1; o < 32; o <<= 1) {
            int t = __shfl_up_sync(0xffffffffu, s2, o);
            if (tid >= o) s2 += t;
        }
        // exclusive prefix for block b = inclusive(b-1)
        int b = blockIdx.x;
        int excl;
        if (b == 0) excl = 0;
        else if (b <= 32) excl = __shfl_sync(0xffffffffu, s, b - 1);
        else excl = total32 + __shfl_sync(0xffffffffu, s2, b - 33);
        if (tid == 0) base_sh = excl;
    }
    __syncthreads();
    int i = blockIdx.x * SCAN_BLOCK + tid;
    if (i < N_NODES) g_off[i] += base_sh;
    if (i == 0) g_off[N_NODES] = N_EDGES;
}

__global__ void scatter_kernel(const int* __restrict__ ei) {
    int e = blockIdx.x * blockDim.x + threadIdx.x;
    if (e < N_EDGES) {
        int dst = ei[N_EDGES + e];
        int pos = g_off[dst] + atomicAdd(&g_fill[dst], 1);
        g_order[pos] = e;
    }
    if (e < N_NODES) g_cnt[e] = 0;
}

// ---------------- edge aggregation: REGISTER accumulators (R15 exact) --------
template<int K, int B>
__device__ __forceinline__ void upd(ull* acc, float4 Bv, ull xv) {
    if constexpr (B < (K - 1) * (K - 1)) {
        constexpr int c0 = B % (K - 1);
        constexpr int c1 = B / (K - 1);
        fma2(acc[c1 * K + c0],           pack2(Bv.x), xv);
        fma2(acc[(c1 + 1) * K + c0],     pack2(Bv.y), xv);
        fma2(acc[c1 * K + c0 + 1],       pack2(Bv.z), xv);
        fma2(acc[(c1 + 1) * K + c0 + 1], pack2(Bv.w), xv);
    }
}

template<int K>
__global__ void __launch_bounds__(64)
aggregate_kernel(const __half* __restrict__ hin,
                 const int* __restrict__ ei,
                 const float* __restrict__ ea) {
    const int KE = K * K;
    __shared__ int    m_meta[2][32];
    __shared__ float4 m_B[2][32];

    int g = threadIdx.x >> 5;
    int lane = threadIdx.x & 31;
    int n = blockIdx.x * 2 + g;
    bool active = n < N_NODES;

    ull acc[KE];
#pragma unroll
    for (int k = 0; k < KE; k++) acc[k] = 0ULL;

    int e0 = 0, e1 = 0;
    if (active) { e0 = g_off[n]; e1 = g_off[n + 1]; }

    const __half2* hin2 = reinterpret_cast<const __half2*>(hin);

    for (int c = e0; c < e1; c += 32) {
        int cnt = min(32, e1 - c);
        if (lane < cnt) {
            int e = g_order[c + lane];
            int src = ei[e];
            float p0 = ea[2 * e + 0];
            float p1 = ea[2 * e + 1];

            float v0 = p0 * (float)(K - 1);
            int l0 = min((int)v0, K - 2);
            float f0 = v0 - (float)l0;
            float v1 = p1 * (float)(K - 1);
            int l1 = min((int)v1, K - 2);
            float f1 = v1 - (float)l1;

            float b00 = 1.0f - f0, b01 = f0;
            float b10 = 1.0f - f1, b11 = f1;

            m_meta[g][lane] = src | ((l0 + l1 * (K - 1)) << 20);
            m_B[g][lane] = make_float4(b00 * b10, b00 * b11, b01 * b10, b01 * b11);
        }
        __syncwarp();

        int meta_n = m_meta[g][0];
        __half2 x_n = hin2[(size_t)(meta_n & 0xFFFFF) * 32 + lane];
        for (int j = 0; j < cnt; j++) {
            int meta = meta_n;
            __half2 xh = x_n;
            float4 Bv = m_B[g][j];
            if (j + 1 < cnt) {
                meta_n = m_meta[g][j + 1];
                x_n = hin2[(size_t)(meta_n & 0xFFFFF) * 32 + lane];
            }
            float2 xf = __half22float2(xh);
            ull xv = packf2(xf.x, xf.y);
            switch (meta >> 20) {
                case 0:  upd<K, 0>(acc, Bv, xv);  break;
                case 1:  upd<K, 1>(acc, Bv, xv);  break;
                case 2:  upd<K, 2>(acc, Bv, xv);  break;
                case 3:  upd<K, 3>(acc, Bv, xv);  break;
                case 4:  upd<K, 4>(acc, Bv, xv);  break;
                case 5:  upd<K, 5>(acc, Bv, xv);  break;
                case 6:  upd<K, 6>(acc, Bv, xv);  break;
                case 7:  upd<K, 7>(acc, Bv, xv);  break;
                case 8:  upd<K, 8>(acc, Bv, xv);  break;
                case 9:  upd<K, 9>(acc, Bv, xv);  break;
                case 10: upd<K, 10>(acc, Bv, xv); break;
                case 11: upd<K, 11>(acc, Bv, xv); break;
                case 12: upd<K, 12>(acc, Bv, xv); break;
                case 13: upd<K, 13>(acc, Bv, xv); break;
                case 14: upd<K, 14>(acc, Bv, xv); break;
                case 15: upd<K, 15>(acc, Bv, xv); break;
                default: break;
            }
        }
        __syncwarp();
    }

    if (active) {
        float invc = 1.0f / fmaxf((float)(e1 - e0), 1.0f);
        __half* zout = g_Z + (size_t)n * KE * D + 2 * lane;
#pragma unroll
        for (int k = 0; k < KE; k++) {
            float2 v = unpack2(acc[k]);
            *reinterpret_cast<__half2*>(zout + k * D) =
                __floats2half2_rn(v.x * invc, v.y * invc);
        }
    }
}

// ---------------- tensor-core GEMM: 128-node M-tile (R15 exact) ---------------
template<int KE>
__global__ void __launch_bounds__(256)
gemm_kernel(const __half* __restrict__ Z,
            const __half* __restrict__ hf,
            const __half* __restrict__ Wt,
            const float* __restrict__ bias,
            __half* __restrict__ houtH) {
    const int KS = KE + 1;
    extern __shared__ __align__(16) char smraw[];

    const int tid = threadIdx.x;
    const int warp = tid >> 5, lane = tid & 31;
    const int n0 = blockIdx.x * GEMM_BN;
    const int m_base = warp * 16;

    float d[32];
#pragma unroll
    for (int i = 0; i < 32; i++) d[i] = 0.0f;

    const unsigned s0 = (unsigned)__cvta_generic_to_shared(smraw);
    const unsigned a_lane = s0
        + (m_base + (lane & 7) + ((lane >> 3) & 1) * 8) * 144 + (lane >> 4) * 16;
    const unsigned b_lane = s0 + GEMM_BOFF
        + ((lane & 7) + ((lane >> 3) & 1) * 8) * 144 + (lane >> 4) * 16;

    auto prefetch = [&](int k, int stage) {
#pragma unroll
        for (int i = 0; i < 4; i++) {
            int c = tid + i * 256;
            int row = c >> 3, q = c & 7;
            int n = n0 + row;
            if (n > N_NODES - 1) n = N_NODES - 1;
            const __half* src = (k < KE)
                ? (Z + ((size_t)n * KE + k) * D + q * 8)
                : (hf + (size_t)n * D + q * 8);
            unsigned sa = s0 + stage * GEMM_ASTG + row * 144 + q * 16;
            asm volatile("cp.async.ca.shared.global [%0], [%1], 16;" :: "r"(sa), "l"(src));
        }
        const __half* wsrc = Wt + (size_t)k * 4096;
#pragma unroll
        for (int i = 0; i < 2; i++) {
            int c = tid + i * 256;
            int row = c >> 3, q = c & 7;
            unsigned sa = s0 + GEMM_BOFF + stage * GEMM_BSTG + row * 144 + q * 16;
            asm volatile("cp.async.ca.shared.global [%0], [%1], 16;" :: "r"(sa), "l"(wsrc + row * 64 + q * 8));
        }
        asm volatile("cp.async.commit_group;");
    };

    prefetch(0, 0);
    int buf = 0;
    for (int k = 0; k < KS; k++) {
        if (k + 1 < KS) {
            prefetch(k + 1, buf ^ 1);
            asm volatile("cp.async.wait_group 1;");
        } else {
            asm volatile("cp.async.wait_group 0;");
        }
        __syncthreads();

        unsigned ab = a_lane + buf * GEMM_ASTG;
        unsigned bb = b_lane + buf * GEMM_BSTG;
#pragma unroll
        for (int kc = 0; kc < 4; kc++) {
            unsigned a0, a1, a2, a3;
            LDSM4(a0, a1, a2, a3, ab + kc * 32);
#pragma unroll
            for (int nt2 = 0; nt2 < 4; nt2++) {
                unsigned r0, r1, r2, r3;
                LDSM4(r0, r1, r2, r3, bb + nt2 * 2304 + kc * 32);
                MMA16816((d + (2 * nt2) * 4),     a0, a1, a2, a3, r0, r2);
                MMA16816((d + (2 * nt2 + 1) * 4), a0, a1, a2, a3, r1, r3);
            }
        }
        __syncthreads();
        buf ^= 1;
    }

    const int g = lane >> 2;
    const int tig = lane & 3;
    const int nA = n0 + m_base + g;
    const int nB = nA + 8;
#pragma unroll
    for (int nt = 0; nt < 8; nt++) {
        int ncol = nt * 8 + 2 * tig;
        float bb0 = bias[ncol], bb1 = bias[ncol + 1];
        float v00 = d[nt * 4 + 0] + bb0;
        float v01 = d[nt * 4 + 1] + bb1;
        float v10 = d[nt * 4 + 2] + bb0;
        float v11 = d[nt * 4 + 3] + bb1;
        v00 = (v00 > 0.0f) ? v00 : expm1f(v00);
        v01 = (v01 > 0.0f) ? v01 : expm1f(v01);
        v10 = (v10 > 0.0f) ? v10 : expm1f(v10);
        v11 = (v11 > 0.0f) ? v11 : expm1f(v11);
        if (nA < N_NODES)
            *reinterpret_cast<__half2*>(houtH + (size_t)nA * D + ncol) =
                __floats2half2_rn(v00, v01);
        if (nB < N_NODES)
            *reinterpret_cast<__half2*>(houtH + (size_t)nB * D + ncol) =
                __floats2half2_rn(v10, v11);
    }
}

// ---------------- MLP tail on tensor cores (R14 exact) ------------------------
__global__ void __launch_bounds__(128)
mlp_mma_kernel(const __half* __restrict__ hf,
               const __half* __restrict__ Wm1,
               const __half* __restrict__ Wm2,
               const float* __restrict__ b1,
               const float* __restrict__ b2,
               float* __restrict__ out) {
    __shared__ __align__(16) __half As[64][72];
    __shared__ __align__(16) __half Bs[64][72];
    __shared__ __align__(8)  __half w2s[512];

    const int tid = threadIdx.x;
    const int warp = tid >> 5, lane = tid & 31;
    const int n0 = blockIdx.x * 64;
    const int m_base = warp * 16;

    const unsigned a0s = (unsigned)__cvta_generic_to_shared(&As[0][0]);
    const unsigned b0s = (unsigned)__cvta_generic_to_shared(&Bs[0][0]);

#pragma unroll
    for (int i = 0; i < 4; i++) {
        int c = tid + i * 128;
        int row = c >> 3, q = c & 7;
        int n = n0 + row;
        if (n > N_NODES - 1) n = N_NODES - 1;
        unsigned sa = a0s + row * 144 + q * 16;
        asm volatile("cp.async.ca.shared.global [%0], [%1], 16;" :: "r"(sa), "l"(hf + (size_t)n * D + q * 8));
        unsigned sb = b0s + row * 144 + q * 16;
        asm volatile("cp.async.ca.shared.global [%0], [%1], 16;" :: "r"(sb), "l"(Wm1 + row * 64 + q * 8));
    }
    *reinterpret_cast<ull*>(w2s + tid * 4) = *reinterpret_cast<const ull*>(Wm2 + tid * 4);
    asm volatile("cp.async.commit_group;");
    asm volatile("cp.async.wait_group 0;");
    __syncthreads();

    const unsigned a_lane = a0s
        + (m_base + (lane & 7) + ((lane >> 3) & 1) * 8) * 144 + (lane >> 4) * 16;
    const unsigned b_lane = b0s
        + ((lane & 7) + ((lane >> 3) & 1) * 8) * 144 + (lane >> 4) * 16;

    float d[32];
#pragma unroll
    for (int i = 0; i < 32; i++) d[i] = 0.0f;

#pragma unroll
    for (int kc = 0; kc < 4; kc++) {
        unsigned a0, a1, a2, a3;
        LDSM4(a0, a1, a2, a3, a_lane + kc * 32);
#pragma unroll
        for (int nt2 = 0; nt2 < 4; nt2++) {
            unsigned r0, r1, r2, r3;
            LDSM4(r0, r1, r2, r3, b_lane + nt2 * 2304 + kc * 32);
            MMA16816((d + (2 * nt2) * 4),     a0, a1, a2, a3, r0, r2);
            MMA16816((d + (2 * nt2 + 1) * 4), a0, a1, a2, a3, r1, r3);
        }
    }

    const int g = lane >> 2;
    const int tig = lane & 3;
    float t[32];
#pragma unroll
    for (int nt = 0; nt < 8; nt++) {
        int ncol = nt * 8 + 2 * tig;
        float bb0 = b1[ncol], bb1 = b1[ncol + 1];
        t[nt * 4 + 0] = fmaxf(d[nt * 4 + 0] + bb0, 0.0f);
        t[nt * 4 + 1] = fmaxf(d[nt * 4 + 1] + bb1, 0.0f);
        t[nt * 4 + 2] = fmaxf(d[nt * 4 + 2] + bb0, 0.0f);
        t[nt * 4 + 3] = fmaxf(d[nt * 4 + 3] + bb1, 0.0f);
    }

    float o4[4] = {0.0f, 0.0f, 0.0f, 0.0f};
#pragma unroll
    for (int kc = 0; kc < 4; kc++) {
        int nt0 = 2 * kc, nt1 = 2 * kc + 1;
        unsigned a0 = packh2(t[nt0 * 4 + 0], t[nt0 * 4 + 1]);
        unsigned a1 = packh2(t[nt0 * 4 + 2], t[nt0 * 4 + 3]);
        unsigned a2 = packh2(t[nt1 * 4 + 0], t[nt1 * 4 + 1]);
        unsigned a3 = packh2(t[nt1 * 4 + 2], t[nt1 * 4 + 3]);
        int k0 = 16 * kc + 2 * tig;
        unsigned bf0 = packh2(__half2float(w2s[k0 * 8 + g]),
                              __half2float(w2s[(k0 + 1) * 8 + g]));
        unsigned bf1 = packh2(__half2float(w2s[(k0 + 8) * 8 + g]),
                              __half2float(w2s[(k0 + 9) * 8 + g]));
        MMA16816(o4, a0, a1, a2, a3, bf0, bf1);
    }

    const int nA = n0 + m_base + g;
    const int nB = nA + 8;
    float bb0 = b2[2 * tig], bb1 = b2[2 * tig + 1];
    if (nA < N_NODES)
        *reinterpret_cast<float2*>(out + (size_t)nA * C + 2 * tig) =
            make_float2(fmaxf(o4[0] + bb0, 0.0f), fmaxf(o4[1] + bb1, 0.0f));
    if (nB < N_NODES)
        *reinterpret_cast<float2*>(out + (size_t)nB * C + 2 * tig) =
            make_float2(fmaxf(o4[2] + bb0, 0.0f), fmaxf(o4[3] + bb1, 0.0f));
}

// ---------------- launch -----------------------------------------------------
extern "C" void kernel_launch(void* const* d_in, const int* in_sizes, int n_in,
                              void* d_out, int out_size) {
    const float* x     = (const float*)d_in[0];
    const int*   ei    = (const int*)  d_in[1];
    const float* ea    = (const float*)d_in[2];
    const float* W1    = (const float*)d_in[3];
    const float* root1 = (const float*)d_in[4];
    const float* b1    = (const float*)d_in[5];
    const float* W2    = (const float*)d_in[6];
    const float* root2 = (const float*)d_in[7];
    const float* b2    = (const float*)d_in[8];
    const float* m1w   = (const float*)d_in[9];
    const float* m1b   = (const float*)d_in[10];
    const float* m2w   = (const float*)d_in[11];
    const float* m2b   = (const float*)d_in[12];
    float* out = (float*)d_out;

    __half* gZ;   cudaGetSymbolAddress((void**)&gZ, g_Z);
    __half* ghf;  cudaGetSymbolAddress((void**)&ghf, g_hf);
    __half* gWt1; cudaGetSymbolAddress((void**)&gWt1, g_Wt1);
    __half* gWt2; cudaGetSymbolAddress((void**)&gWt2, g_Wt2);
    __half* gWm1; cudaGetSymbolAddress((void**)&gWm1, g_Wm1);
    __half* gWm2; cudaGetSymbolAddress((void**)&gWm2, g_Wm2);

    cudaFuncSetAttribute((const void*)gemm_kernel<9>,
                         cudaFuncAttributeMaxDynamicSharedMemorySize, GEMM_SMEM);
    cudaFuncSetAttribute((const void*)gemm_kernel<25>,
                         cudaFuncAttributeMaxDynamicSharedMemorySize, GEMM_SMEM);

    const int GEMM_BLOCKS = (N_NODES + GEMM_BN - 1) / GEMM_BN;   // 391
    const int AGG_BLOCKS  = (N_NODES + 1) / 2;                   // 25000
    const int MLP_BLOCKS  = (N_NODES + 63) / 64;                 // 782
    const int EB = (N_EDGES + 255) / 256;                        // 3125

    // ---- CSR build: 4 launches (convw folded into scan1; scan2+3 merged) ----
    hist_kernel<<<EB, 256>>>(ei, x);
    scan1_kernel<<<SCAN_NBLK, SCAN_BLOCK>>>(W1, root1, W2, root2, m1w, m2w);
    scan23_kernel<<<SCAN_NBLK, SCAN_BLOCK>>>();
    scatter_kernel<<<EB, 256>>>(ei);

    // ---- Layer 1 (K=3) ----
    aggregate_kernel<3><<<AGG_BLOCKS, 64>>>(ghf, ei, ea);
    gemm_kernel<9><<<GEMM_BLOCKS, 256, GEMM_SMEM>>>(gZ, ghf, gWt1, b1, ghf);

    // ---- Layer 2 (K=5) ----
    aggregate_kernel<5><<<AGG_BLOCKS, 64>>>(ghf, ei, ea);
    gemm_kernel<25><<<GEMM_BLOCKS, 256, GEMM_SMEM>>>(gZ, ghf, gWt2, b2, ghf);

    // ---- MLP tail on tensor cores ----
    mlp_mma_kernel<<<MLP_BLOCKS, 128>>>(ghf, gWm1, gWm2, m1b, m2b, out);
}